// round 6
// baseline (speedup 1.0000x reference)
#include <cuda_runtime.h>
#include <math.h>

#define NMAX 100000
#define ACC_W 16   // [coeff, edge_sca*coeff (6), edge_vec*coeff (9)]
#define EPB 256    // edges per block in edge kernel

__device__ __align__(16) float g_acc[NMAX * ACC_W];   // zero-initialized at load

// ---------------------------------------------------------------------------
// Edge phase (unchanged from R4 winner): staged coalesced loads + red.v4
// ---------------------------------------------------------------------------
__device__ __forceinline__ void red_v4(float* p, float a, float b, float c, float d) {
    asm volatile("red.global.add.v4.f32 [%0], {%1,%2,%3,%4};"
                 :: "l"(p), "f"(a), "f"(b), "f"(c), "f"(d) : "memory");
}

__global__ void __launch_bounds__(EPB)
edge_kernel(const float* __restrict__ edge_sca,
            const float* __restrict__ edge_vec,
            const float* __restrict__ gds,
            const int*   __restrict__ src_idx,
            int E) {
    __shared__ float s_sca[EPB * 6];
    __shared__ float s_vec[EPB * 9];

    int blockStart = blockIdx.x * EPB;
    int tid = threadIdx.x;
    int nEdges = min(EPB, E - blockStart);

    if (nEdges == EPB) {
        const float4* g4s = (const float4*)(edge_sca + (size_t)blockStart * 6);
        float4* s4s = (float4*)s_sca;
#pragma unroll 2
        for (int i = tid; i < (EPB * 6) / 4; i += EPB)
            s4s[i] = g4s[i];
        const float4* g4v = (const float4*)(edge_vec + (size_t)blockStart * 9);
        float4* s4v = (float4*)s_vec;
#pragma unroll 3
        for (int i = tid; i < (EPB * 9) / 4; i += EPB)
            s4v[i] = g4v[i];
    } else {
        for (int i = tid; i < nEdges * 6; i += EPB)
            s_sca[i] = edge_sca[(size_t)blockStart * 6 + i];
        for (int i = tid; i < nEdges * 9; i += EPB)
            s_vec[i] = edge_vec[(size_t)blockStart * 9 + i];
    }
    __syncthreads();

    if (tid >= nEdges) return;
    int e = blockStart + tid;

    float dist = __ldg(gds + e);
    if (dist > 10.0f || dist < 0.0f) return;
    float coeff = 0.5f * (__cosf(dist * 0.31415926535f) + 1.0f);

    int src = __ldg(src_idx + e);

    float es[6];
#pragma unroll
    for (int c = 0; c < 6; c++) es[c] = s_sca[tid * 6 + c] * coeff;
    float ev[9];
#pragma unroll
    for (int c = 0; c < 9; c++) ev[c] = s_vec[tid * 9 + c] * coeff;

    float* base = g_acc + (size_t)src * ACC_W;
    red_v4(base + 0,  coeff, es[0], es[1], es[2]);
    red_v4(base + 4,  es[3], es[4], es[5], ev[0]);
    red_v4(base + 8,  ev[1], ev[2], ev[3], ev[4]);
    red_v4(base + 12, ev[5], ev[6], ev[7], ev[8]);
}

// ---------------------------------------------------------------------------
// Node phase: 4 LANES PER NODE. Lane j owns output channels {4j..4j+3} of
// every stage; full-width intermediates exchanged via padded per-node SMEM
// buffers with __syncwarp() between phases. Re-zeroes g_acc after consuming.
// ---------------------------------------------------------------------------
#define O_NSS   0      // 4x16
#define O_BNSS  64     // 16
#define O_ESS   80     // 6x16
#define O_BESS  176    // 16
#define O_NSV   192    // 4x16
#define O_BNSV  256    // 16
#define O_ESV   272    // 6x16
#define O_BESV  368    // 16
#define O_NVV   384    // 3x16
#define O_EVV   432    // 3x16
#define O_LV    480    // 16x16
#define O_LV2   736    // 16x16
#define O_LS    992    // 32x16
#define O_GATE  1504   // 16x16
#define O_BGATE 1760   // 16
#define O_DIR   1776   // 16x16
#define SW_TOT  2032

#define NPB 32         // nodes per block
#define TPB 128        // threads per block (4 per node)
#define BUF_W 68       // 64 payload + 4 pad (stride 68 -> conflict-free across nodes)

__global__ void __launch_bounds__(TPB)
node_kernel(const float* __restrict__ node_sca,
            const float* __restrict__ node_vec,
            const float* __restrict__ W_nss, const float* __restrict__ b_nss,
            const float* __restrict__ W_ess, const float* __restrict__ b_ess,
            const float* __restrict__ W_nsv, const float* __restrict__ b_nsv,
            const float* __restrict__ W_esv, const float* __restrict__ b_esv,
            const float* __restrict__ W_nvv, const float* __restrict__ W_evv,
            const float* __restrict__ W_lv,  const float* __restrict__ W_lv2,
            const float* __restrict__ W_ls,  const float* __restrict__ W_gate,
            const float* __restrict__ b_gate,const float* __restrict__ W_dir,
            float* __restrict__ out, int N) {
    __shared__ float sW[SW_TOT];
    __shared__ float s_nv[NPB * 9];
    __shared__ float bufA[NPB][BUF_W];   // av/asca -> osca -> ovec
    __shared__ float bufB[NPB][BUF_W];   // v_inter (48) + v_norm (16)

    int tid = threadIdx.x;
    int nd  = tid >> 2;          // node within block
    int j   = tid & 3;           // sub-lane: owns channels o0..o0+3
    int o0  = j * 4;
    int blockStart = blockIdx.x * NPB;
    int nNodes = min(NPB, N - blockStart);
    int n = blockStart + nd;
    bool active = (nd < nNodes);

    {   // weights -> shared
        const float* srcs[16] = {W_nss, b_nss, W_ess, b_ess, W_nsv, b_nsv,
                                 W_esv, b_esv, W_nvv, W_evv, W_lv, W_lv2,
                                 W_ls, W_gate, b_gate, W_dir};
        const int offs[17] = {O_NSS, O_BNSS, O_ESS, O_BESS, O_NSV, O_BNSV,
                              O_ESV, O_BESV, O_NVV, O_EVV, O_LV, O_LV2,
                              O_LS, O_GATE, O_BGATE, O_DIR, SW_TOT};
        for (int a = 0; a < 16; a++) {
            int cnt = offs[a + 1] - offs[a];
            for (int i = tid; i < cnt; i += TPB)
                sW[offs[a] + i] = srcs[a][i];
        }
    }
    {   // node_vec -> shared (coalesced)
        for (int i = tid; i < nNodes * 9; i += TPB)
            s_nv[i] = node_vec[(size_t)blockStart * 9 + i];
    }
    __syncthreads();

    // ---- per-node inputs (broadcast across the node's 4 lanes) ----
    float ns[4] = {0, 0, 0, 0};
    float nv[9] = {0};
    float accv[16] = {0};
    if (active) {
        float4 ns4 = ((const float4*)node_sca)[n];
        ns[0] = ns4.x; ns[1] = ns4.y; ns[2] = ns4.z; ns[3] = ns4.w;
#pragma unroll
        for (int i = 0; i < 9; i++) nv[i] = s_nv[nd * 9 + i];
        const float4* a4 = (const float4*)(g_acc + (size_t)n * ACC_W);
#pragma unroll
        for (int q = 0; q < 4; q++) {
            float4 v = a4[q];
            accv[q * 4 + 0] = v.x; accv[q * 4 + 1] = v.y;
            accv[q * 4 + 2] = v.z; accv[q * 4 + 3] = v.w;
        }
    }
    __syncwarp();
    if (active)   // zero quarter j for next graph replay (after all lanes read)
        ((float4*)(g_acc + (size_t)n * ACC_W))[j] = make_float4(0.f, 0.f, 0.f, 0.f);

    float Cs = accv[0];
    float* Es = accv + 1;      // 6
    float* Ev = accv + 7;      // 3x3 row-major [c*3+i]

    // ---- Phase 1: this lane computes aggr channels c in {4j..4j+3} ----
    if (active) {
#pragma unroll
        for (int cc = 0; cc < 4; cc++) {
            int c = o0 + cc;
            float nss = sW[O_BNSS + c];
            float nsv = sW[O_BNSV + c];
#pragma unroll
            for (int k = 0; k < 4; k++) {
                nss += ns[k] * sW[O_NSS + k * 16 + c];
                nsv += ns[k] * sW[O_NSV + k * 16 + c];
            }
            float ess = sW[O_BESS + c] * Cs;
            float esv = sW[O_BESV + c] * Cs;
#pragma unroll
            for (int k = 0; k < 6; k++) {
                ess += Es[k] * sW[O_ESS + k * 16 + c];
                esv += Es[k] * sW[O_ESV + k * 16 + c];
            }
            bufA[nd][c * 4 + 3] = nss * ess;          // aggr_sca[c]
#pragma unroll
            for (int i = 0; i < 3; i++) {
                float nvv = 0.f, evv = 0.f;
#pragma unroll
                for (int k = 0; k < 3; k++) {
                    nvv += nv[k * 3 + i] * sW[O_NVV + k * 16 + c];
                    evv += Ev[k * 3 + i] * sW[O_EVV + k * 16 + c];
                }
                bufA[nd][c * 4 + i] = nvv * esv + nsv * evv;   // aggr_vec[c][i]
            }
        }
    }
    __syncwarp();

    // ---- Phase 2: lv + ls-scalar-half for own 4 output channels ----
    float vi[4][3];
    float osca[4];
#pragma unroll
    for (int oo = 0; oo < 4; oo++) {
        vi[oo][0] = 0.f; vi[oo][1] = 0.f; vi[oo][2] = 0.f; osca[oo] = 0.f;
    }
    if (active) {
#pragma unroll
        for (int c = 0; c < 16; c++) {
            float a0 = bufA[nd][c * 4 + 0];
            float a1 = bufA[nd][c * 4 + 1];
            float a2 = bufA[nd][c * 4 + 2];
            float as = bufA[nd][c * 4 + 3];
#pragma unroll
            for (int oo = 0; oo < 4; oo++) {
                float wlv = sW[O_LV + c * 16 + o0 + oo];
                vi[oo][0] += a0 * wlv;
                vi[oo][1] += a1 * wlv;
                vi[oo][2] += a2 * wlv;
                osca[oo]  += as * sW[O_LS + (c + 16) * 16 + o0 + oo];
            }
        }
#pragma unroll
        for (int oo = 0; oo < 4; oo++) {
            bufB[nd][(o0 + oo) * 3 + 0] = vi[oo][0];
            bufB[nd][(o0 + oo) * 3 + 1] = vi[oo][1];
            bufB[nd][(o0 + oo) * 3 + 2] = vi[oo][2];
            bufB[nd][48 + o0 + oo] = sqrtf(vi[oo][0] * vi[oo][0] +
                                           vi[oo][1] * vi[oo][1] +
                                           vi[oo][2] * vi[oo][2]);
        }
    }
    __syncwarp();

    // ---- Phase 3: osca (v_norm half); publish osca to bufA[0..15] ----
    if (active) {
#pragma unroll
        for (int c = 0; c < 16; c++) {
            float vn = bufB[nd][48 + c];
#pragma unroll
            for (int oo = 0; oo < 4; oo++)
                osca[oo] += vn * sW[O_LS + c * 16 + o0 + oo];
        }
    }
    __syncwarp();   // av reads done; safe to overwrite bufA
    if (active) {
#pragma unroll
        for (int oo = 0; oo < 4; oo++) bufA[nd][o0 + oo] = osca[oo];
    }
    __syncwarp();

    // ---- Phase 4: gate ----
    float gate[4];
#pragma unroll
    for (int oo = 0; oo < 4; oo++) gate[oo] = sW[O_BGATE + o0 + oo];
    if (active) {
#pragma unroll
        for (int c = 0; c < 16; c++) {
            float oc = bufA[nd][c];
#pragma unroll
            for (int oo = 0; oo < 4; oo++)
                gate[oo] += oc * sW[O_GATE + c * 16 + o0 + oo];
        }
    }
#pragma unroll
    for (int oo = 0; oo < 4; oo++) gate[oo] = 1.0f / (1.0f + __expf(-gate[oo]));
    __syncwarp();   // osca reads done; safe to overwrite bufA with ovec

    // ---- Phase 5: lv2 -> ovec (gated); publish ovec to bufA[0..47] ----
    float ov[4][3];
#pragma unroll
    for (int oo = 0; oo < 4; oo++) { ov[oo][0] = 0.f; ov[oo][1] = 0.f; ov[oo][2] = 0.f; }
    if (active) {
#pragma unroll
        for (int c = 0; c < 16; c++) {
            float v0 = bufB[nd][c * 3 + 0];
            float v1 = bufB[nd][c * 3 + 1];
            float v2 = bufB[nd][c * 3 + 2];
#pragma unroll
            for (int oo = 0; oo < 4; oo++) {
                float w = sW[O_LV2 + c * 16 + o0 + oo];
                ov[oo][0] += v0 * w;
                ov[oo][1] += v1 * w;
                ov[oo][2] += v2 * w;
            }
        }
#pragma unroll
        for (int oo = 0; oo < 4; oo++) {
            ov[oo][0] *= gate[oo]; ov[oo][1] *= gate[oo]; ov[oo][2] *= gate[oo];
            bufA[nd][(o0 + oo) * 3 + 0] = ov[oo][0];
            bufA[nd][(o0 + oo) * 3 + 1] = ov[oo][1];
            bufA[nd][(o0 + oo) * 3 + 2] = ov[oo][2];
        }
    }
    __syncwarp();

    // ---- Phase 6: VNLeakyReLU direction + writes ----
    if (!active) return;
    float d[4][3];
#pragma unroll
    for (int oo = 0; oo < 4; oo++) { d[oo][0] = 0.f; d[oo][1] = 0.f; d[oo][2] = 0.f; }
#pragma unroll
    for (int c = 0; c < 16; c++) {
        float v0 = bufA[nd][c * 3 + 0];
        float v1 = bufA[nd][c * 3 + 1];
        float v2 = bufA[nd][c * 3 + 2];
#pragma unroll
        for (int oo = 0; oo < 4; oo++) {
            float w = sW[O_DIR + c * 16 + o0 + oo];
            d[oo][0] += v0 * w;
            d[oo][1] += v1 * w;
            d[oo][2] += v2 * w;
        }
    }

    float res[12];
#pragma unroll
    for (int oo = 0; oo < 4; oo++) {
        float v0 = ov[oo][0], v1 = ov[oo][1], v2 = ov[oo][2];
        float d0 = d[oo][0], d1 = d[oo][1], d2 = d[oo][2];
        float dot = v0 * d0 + v1 * d1 + v2 * d2;
        float r0 = v0, r1 = v1, r2 = v2;
        if (dot < 0.0f) {
            float k = 0.8f * dot / (d0 * d0 + d1 * d1 + d2 * d2 + 1e-6f);
            r0 = v0 - k * d0; r1 = v1 - k * d1; r2 = v2 - k * d2;
        }
        res[oo * 3 + 0] = r0; res[oo * 3 + 1] = r1; res[oo * 3 + 2] = r2;
    }

    // vector out: lane covers bytes [n*48 + j*12, +12) -> 3 float4, coalesced
    float* out_vec = out + (size_t)N * 16;
    float4* dv = (float4*)(out_vec + (size_t)n * 48 + j * 12);
#pragma unroll
    for (int q = 0; q < 3; q++)
        dv[q] = make_float4(res[q * 4 + 0], res[q * 4 + 1],
                            res[q * 4 + 2], res[q * 4 + 3]);

    // scalar out: own 4 channels, one float4, coalesced
    float s0 = osca[0], s1 = osca[1], s2 = osca[2], s3 = osca[3];
    s0 = (s0 >= 0.f) ? s0 : 0.01f * s0;
    s1 = (s1 >= 0.f) ? s1 : 0.01f * s1;
    s2 = (s2 >= 0.f) ? s2 : 0.01f * s2;
    s3 = (s3 >= 0.f) ? s3 : 0.01f * s3;
    ((float4*)(out + (size_t)n * 16 + o0))[0] = make_float4(s0, s1, s2, s3);
}

// ---------------------------------------------------------------------------
extern "C" void kernel_launch(void* const* d_in, const int* in_sizes, int n_in,
                              void* d_out, int out_size) {
    const float* node_sca = (const float*)d_in[0];
    const float* node_vec = (const float*)d_in[1];
    const float* edge_sca = (const float*)d_in[2];
    const float* edge_vec = (const float*)d_in[3];
    const float* gds      = (const float*)d_in[4];
    const int*   ei       = (const int*)d_in[5];   // [2,E]; row 0 = src
    const float* W_nss  = (const float*)d_in[6];
    const float* b_nss  = (const float*)d_in[7];
    const float* W_ess  = (const float*)d_in[8];
    const float* b_ess  = (const float*)d_in[9];
    const float* W_nsv  = (const float*)d_in[10];
    const float* b_nsv  = (const float*)d_in[11];
    const float* W_esv  = (const float*)d_in[12];
    const float* b_esv  = (const float*)d_in[13];
    const float* W_nvv  = (const float*)d_in[14];
    const float* W_evv  = (const float*)d_in[15];
    const float* W_lv   = (const float*)d_in[16];
    const float* W_lv2  = (const float*)d_in[17];
    const float* W_ls   = (const float*)d_in[18];
    const float* W_gate = (const float*)d_in[19];
    const float* b_gate = (const float*)d_in[20];
    const float* W_dir  = (const float*)d_in[21];

    int N = in_sizes[0] / 4;
    int E = in_sizes[4];

    int eblocks = (E + EPB - 1) / EPB;
    edge_kernel<<<eblocks, EPB>>>(edge_sca, edge_vec, gds, ei, E);

    int nblocks = (N + NPB - 1) / NPB;
    node_kernel<<<nblocks, TPB>>>(node_sca, node_vec,
                                  W_nss, b_nss, W_ess, b_ess,
                                  W_nsv, b_nsv, W_esv, b_esv,
                                  W_nvv, W_evv, W_lv, W_lv2,
                                  W_ls, W_gate, b_gate, W_dir,
                                  (float*)d_out, N);
}

// round 7
// speedup vs baseline: 1.0320x; 1.0320x over previous
#include <cuda_runtime.h>
#include <math.h>

#define NMAX 100000
#define ACC_W 16   // [coeff, edge_sca*coeff (6), edge_vec*coeff (9)]
#define EPB 256    // edges per block in edge kernel

__device__ __align__(16) float g_acc[NMAX * ACC_W];   // zero-initialized at load

// ---------------------------------------------------------------------------
// Edge phase (unchanged): staged coalesced loads + red.v4
// ---------------------------------------------------------------------------
__device__ __forceinline__ void red_v4(float* p, float a, float b, float c, float d) {
    asm volatile("red.global.add.v4.f32 [%0], {%1,%2,%3,%4};"
                 :: "l"(p), "f"(a), "f"(b), "f"(c), "f"(d) : "memory");
}

__global__ void __launch_bounds__(EPB)
edge_kernel(const float* __restrict__ edge_sca,
            const float* __restrict__ edge_vec,
            const float* __restrict__ gds,
            const int*   __restrict__ src_idx,
            int E) {
    __shared__ float s_sca[EPB * 6];
    __shared__ float s_vec[EPB * 9];

    int blockStart = blockIdx.x * EPB;
    int tid = threadIdx.x;
    int nEdges = min(EPB, E - blockStart);

    if (nEdges == EPB) {
        const float4* g4s = (const float4*)(edge_sca + (size_t)blockStart * 6);
        float4* s4s = (float4*)s_sca;
#pragma unroll 2
        for (int i = tid; i < (EPB * 6) / 4; i += EPB)
            s4s[i] = g4s[i];
        const float4* g4v = (const float4*)(edge_vec + (size_t)blockStart * 9);
        float4* s4v = (float4*)s_vec;
#pragma unroll 3
        for (int i = tid; i < (EPB * 9) / 4; i += EPB)
            s4v[i] = g4v[i];
    } else {
        for (int i = tid; i < nEdges * 6; i += EPB)
            s_sca[i] = edge_sca[(size_t)blockStart * 6 + i];
        for (int i = tid; i < nEdges * 9; i += EPB)
            s_vec[i] = edge_vec[(size_t)blockStart * 9 + i];
    }
    __syncthreads();

    if (tid >= nEdges) return;
    int e = blockStart + tid;

    float dist = __ldg(gds + e);
    if (dist > 10.0f || dist < 0.0f) return;
    float coeff = 0.5f * (__cosf(dist * 0.31415926535f) + 1.0f);

    int src = __ldg(src_idx + e);

    float es[6];
#pragma unroll
    for (int c = 0; c < 6; c++) es[c] = s_sca[tid * 6 + c] * coeff;
    float ev[9];
#pragma unroll
    for (int c = 0; c < 9; c++) ev[c] = s_vec[tid * 9 + c] * coeff;

    float* base = g_acc + (size_t)src * ACC_W;
    red_v4(base + 0,  coeff, es[0], es[1], es[2]);
    red_v4(base + 4,  es[3], es[4], es[5], ev[0]);
    red_v4(base + 8,  ev[1], ev[2], ev[3], ev[4]);
    red_v4(base + 12, ev[5], ev[6], ev[7], ev[8]);
}

// ---------------------------------------------------------------------------
// Node phase: 4 lanes per node, ALL smem traffic 128-bit.
// Exchange buffers use channel-stride-4 layout: slot c -> {x, y, z, aux}.
// ---------------------------------------------------------------------------
#define O_NSS   0      // 4x16
#define O_BNSS  64     // 16
#define O_ESS   80     // 6x16
#define O_BESS  176    // 16
#define O_NSV   192    // 4x16
#define O_BNSV  256    // 16
#define O_ESV   272    // 6x16
#define O_BESV  368    // 16
#define O_NVV   384    // 3x16
#define O_EVV   432    // 3x16
#define O_LV    480    // 16x16
#define O_LV2   736    // 16x16
#define O_LS    992    // 32x16
#define O_GATE  1504   // 16x16
#define O_BGATE 1760   // 16
#define O_DIR   1776   // 16x16
#define SW_TOT  2032

#define NPB 64         // nodes per block
#define TPB 256        // threads per block (4 per node)
#define BUF_W 68       // 64 payload + 4 pad floats (stride 272B, conflict-free)

__global__ void __launch_bounds__(TPB)
node_kernel(const float* __restrict__ node_sca,
            const float* __restrict__ node_vec,
            const float* __restrict__ W_nss, const float* __restrict__ b_nss,
            const float* __restrict__ W_ess, const float* __restrict__ b_ess,
            const float* __restrict__ W_nsv, const float* __restrict__ b_nsv,
            const float* __restrict__ W_esv, const float* __restrict__ b_esv,
            const float* __restrict__ W_nvv, const float* __restrict__ W_evv,
            const float* __restrict__ W_lv,  const float* __restrict__ W_lv2,
            const float* __restrict__ W_ls,  const float* __restrict__ W_gate,
            const float* __restrict__ b_gate,const float* __restrict__ W_dir,
            float* __restrict__ out, int N) {
    __shared__ __align__(16) float sW[SW_TOT];
    __shared__ float s_nv[NPB * 9];
    __shared__ __align__(16) float bufA[NPB][BUF_W];  // aggr -> osca -> ovec
    __shared__ __align__(16) float bufB[NPB][BUF_W];  // v_inter + v_norm

    int tid = threadIdx.x;
    int nd  = tid >> 2;          // node within block
    int j   = tid & 3;           // sub-lane: owns output channels o0..o0+3
    int o0  = j * 4;
    int blockStart = blockIdx.x * NPB;
    int nNodes = min(NPB, N - blockStart);
    int n = blockStart + nd;
    bool active = (nd < nNodes);

    {   // weights -> shared
        const float* srcs[16] = {W_nss, b_nss, W_ess, b_ess, W_nsv, b_nsv,
                                 W_esv, b_esv, W_nvv, W_evv, W_lv, W_lv2,
                                 W_ls, W_gate, b_gate, W_dir};
        const int offs[17] = {O_NSS, O_BNSS, O_ESS, O_BESS, O_NSV, O_BNSV,
                              O_ESV, O_BESV, O_NVV, O_EVV, O_LV, O_LV2,
                              O_LS, O_GATE, O_BGATE, O_DIR, SW_TOT};
        for (int a = 0; a < 16; a++) {
            int cnt = offs[a + 1] - offs[a];
            for (int i = tid; i < cnt; i += TPB)
                sW[offs[a] + i] = srcs[a][i];
        }
    }
    {   // node_vec -> shared (coalesced)
        for (int i = tid; i < nNodes * 9; i += TPB)
            s_nv[i] = node_vec[(size_t)blockStart * 9 + i];
    }
    __syncthreads();

    // ---- per-node inputs (each lane loads a full copy) ----
    float ns[4] = {0, 0, 0, 0};
    float nv[9] = {0};
    float accv[16] = {0};
    if (active) {
        float4 ns4 = ((const float4*)node_sca)[n];
        ns[0] = ns4.x; ns[1] = ns4.y; ns[2] = ns4.z; ns[3] = ns4.w;
#pragma unroll
        for (int i = 0; i < 9; i++) nv[i] = s_nv[nd * 9 + i];
        const float4* a4 = (const float4*)(g_acc + (size_t)n * ACC_W);
#pragma unroll
        for (int q = 0; q < 4; q++) {
            float4 v = a4[q];
            accv[q * 4 + 0] = v.x; accv[q * 4 + 1] = v.y;
            accv[q * 4 + 2] = v.z; accv[q * 4 + 3] = v.w;
        }
    }
    __syncwarp();
    if (active)   // zero quarter j for next graph replay
        ((float4*)(g_acc + (size_t)n * ACC_W))[j] = make_float4(0.f, 0.f, 0.f, 0.f);

    float Cs = accv[0];
    float* Es = accv + 1;
    float* Ev = accv + 7;      // 3x3 row-major [k*3+i]

    // ---- Phase 1: aggr channels c in {4j..4j+3}; STS.128 per channel ----
    if (active) {
#pragma unroll
        for (int cc = 0; cc < 4; cc++) {
            int c = o0 + cc;
            float nss = sW[O_BNSS + c];
            float nsv = sW[O_BNSV + c];
#pragma unroll
            for (int k = 0; k < 4; k++) {
                nss += ns[k] * sW[O_NSS + k * 16 + c];
                nsv += ns[k] * sW[O_NSV + k * 16 + c];
            }
            float ess = sW[O_BESS + c] * Cs;
            float esv = sW[O_BESV + c] * Cs;
#pragma unroll
            for (int k = 0; k < 6; k++) {
                ess += Es[k] * sW[O_ESS + k * 16 + c];
                esv += Es[k] * sW[O_ESV + k * 16 + c];
            }
            float av[3];
#pragma unroll
            for (int i = 0; i < 3; i++) {
                float nvv = 0.f, evv = 0.f;
#pragma unroll
                for (int k = 0; k < 3; k++) {
                    nvv += nv[k * 3 + i] * sW[O_NVV + k * 16 + c];
                    evv += Ev[k * 3 + i] * sW[O_EVV + k * 16 + c];
                }
                av[i] = nvv * esv + nsv * evv;
            }
            *(float4*)&bufA[nd][c * 4] = make_float4(av[0], av[1], av[2], nss * ess);
        }
    }
    __syncwarp();

    // ---- Phase 2: lv + ls-scalar-half (3 x LDS.128 per channel) ----
    float vi[4][3];
    float osca[4];
#pragma unroll
    for (int oo = 0; oo < 4; oo++) {
        vi[oo][0] = 0.f; vi[oo][1] = 0.f; vi[oo][2] = 0.f; osca[oo] = 0.f;
    }
    if (active) {
#pragma unroll
        for (int c = 0; c < 16; c++) {
            float4 a   = *(const float4*)&bufA[nd][c * 4];
            float4 wlv = *(const float4*)&sW[O_LV + c * 16 + o0];
            float4 wls = *(const float4*)&sW[O_LS + (c + 16) * 16 + o0];
            vi[0][0] += a.x * wlv.x; vi[0][1] += a.y * wlv.x; vi[0][2] += a.z * wlv.x;
            vi[1][0] += a.x * wlv.y; vi[1][1] += a.y * wlv.y; vi[1][2] += a.z * wlv.y;
            vi[2][0] += a.x * wlv.z; vi[2][1] += a.y * wlv.z; vi[2][2] += a.z * wlv.z;
            vi[3][0] += a.x * wlv.w; vi[3][1] += a.y * wlv.w; vi[3][2] += a.z * wlv.w;
            osca[0] += a.w * wls.x; osca[1] += a.w * wls.y;
            osca[2] += a.w * wls.z; osca[3] += a.w * wls.w;
        }
#pragma unroll
        for (int oo = 0; oo < 4; oo++) {
            float vn = sqrtf(vi[oo][0] * vi[oo][0] + vi[oo][1] * vi[oo][1] +
                             vi[oo][2] * vi[oo][2]);
            *(float4*)&bufB[nd][(o0 + oo) * 4] =
                make_float4(vi[oo][0], vi[oo][1], vi[oo][2], vn);
        }
    }
    __syncwarp();

    // ---- Phase 3: osca v_norm-half; publish osca (STS.128) ----
    if (active) {
#pragma unroll
        for (int c = 0; c < 16; c++) {
            float vn = bufB[nd][c * 4 + 3];
            float4 wls = *(const float4*)&sW[O_LS + c * 16 + o0];
            osca[0] += vn * wls.x; osca[1] += vn * wls.y;
            osca[2] += vn * wls.z; osca[3] += vn * wls.w;
        }
        *(float4*)&bufA[nd][o0] = make_float4(osca[0], osca[1], osca[2], osca[3]);
    }
    __syncwarp();

    // ---- Phase 4: gate ----
    float gate[4] = {sW[O_BGATE + o0], sW[O_BGATE + o0 + 1],
                     sW[O_BGATE + o0 + 2], sW[O_BGATE + o0 + 3]};
    if (active) {
#pragma unroll
        for (int c4 = 0; c4 < 4; c4++) {
            float4 oc = *(const float4*)&bufA[nd][c4 * 4];
            float ocv[4] = {oc.x, oc.y, oc.z, oc.w};
#pragma unroll
            for (int q = 0; q < 4; q++) {
                float4 wg = *(const float4*)&sW[O_GATE + (c4 * 4 + q) * 16 + o0];
                gate[0] += ocv[q] * wg.x; gate[1] += ocv[q] * wg.y;
                gate[2] += ocv[q] * wg.z; gate[3] += ocv[q] * wg.w;
            }
        }
    }
#pragma unroll
    for (int oo = 0; oo < 4; oo++) gate[oo] = 1.0f / (1.0f + __expf(-gate[oo]));
    __syncwarp();   // osca reads done; bufA reusable for ovec

    // ---- Phase 5: lv2 -> ovec (gated); publish (STS.128) ----
    float ov[4][3];
#pragma unroll
    for (int oo = 0; oo < 4; oo++) { ov[oo][0] = 0.f; ov[oo][1] = 0.f; ov[oo][2] = 0.f; }
    if (active) {
#pragma unroll
        for (int c = 0; c < 16; c++) {
            float4 v = *(const float4*)&bufB[nd][c * 4];   // vi0,vi1,vi2,norm
            float4 w = *(const float4*)&sW[O_LV2 + c * 16 + o0];
            ov[0][0] += v.x * w.x; ov[0][1] += v.y * w.x; ov[0][2] += v.z * w.x;
            ov[1][0] += v.x * w.y; ov[1][1] += v.y * w.y; ov[1][2] += v.z * w.y;
            ov[2][0] += v.x * w.z; ov[2][1] += v.y * w.z; ov[2][2] += v.z * w.z;
            ov[3][0] += v.x * w.w; ov[3][1] += v.y * w.w; ov[3][2] += v.z * w.w;
        }
#pragma unroll
        for (int oo = 0; oo < 4; oo++) {
            ov[oo][0] *= gate[oo]; ov[oo][1] *= gate[oo]; ov[oo][2] *= gate[oo];
            *(float4*)&bufA[nd][(o0 + oo) * 4] =
                make_float4(ov[oo][0], ov[oo][1], ov[oo][2], 0.f);
        }
    }
    __syncwarp();

    // ---- Phase 6: direction + VNLeakyReLU + writes ----
    if (!active) return;
    float d[4][3];
#pragma unroll
    for (int oo = 0; oo < 4; oo++) { d[oo][0] = 0.f; d[oo][1] = 0.f; d[oo][2] = 0.f; }
#pragma unroll
    for (int c = 0; c < 16; c++) {
        float4 v = *(const float4*)&bufA[nd][c * 4];
        float4 w = *(const float4*)&sW[O_DIR + c * 16 + o0];
        d[0][0] += v.x * w.x; d[0][1] += v.y * w.x; d[0][2] += v.z * w.x;
        d[1][0] += v.x * w.y; d[1][1] += v.y * w.y; d[1][2] += v.z * w.y;
        d[2][0] += v.x * w.z; d[2][1] += v.y * w.z; d[2][2] += v.z * w.z;
        d[3][0] += v.x * w.w; d[3][1] += v.y * w.w; d[3][2] += v.z * w.w;
    }

    float res[12];
#pragma unroll
    for (int oo = 0; oo < 4; oo++) {
        float v0 = ov[oo][0], v1 = ov[oo][1], v2 = ov[oo][2];
        float d0 = d[oo][0], d1 = d[oo][1], d2 = d[oo][2];
        float dot = v0 * d0 + v1 * d1 + v2 * d2;
        float r0 = v0, r1 = v1, r2 = v2;
        if (dot < 0.0f) {
            float k = 0.8f * dot / (d0 * d0 + d1 * d1 + d2 * d2 + 1e-6f);
            r0 = v0 - k * d0; r1 = v1 - k * d1; r2 = v2 - k * d2;
        }
        res[oo * 3 + 0] = r0; res[oo * 3 + 1] = r1; res[oo * 3 + 2] = r2;
    }

    float* out_vec = out + (size_t)N * 16;
    float4* dv = (float4*)(out_vec + (size_t)n * 48 + j * 12);
#pragma unroll
    for (int q = 0; q < 3; q++)
        dv[q] = make_float4(res[q * 4 + 0], res[q * 4 + 1],
                            res[q * 4 + 2], res[q * 4 + 3]);

    float s0 = osca[0], s1 = osca[1], s2 = osca[2], s3 = osca[3];
    s0 = (s0 >= 0.f) ? s0 : 0.01f * s0;
    s1 = (s1 >= 0.f) ? s1 : 0.01f * s1;
    s2 = (s2 >= 0.f) ? s2 : 0.01f * s2;
    s3 = (s3 >= 0.f) ? s3 : 0.01f * s3;
    ((float4*)(out + (size_t)n * 16 + o0))[0] = make_float4(s0, s1, s2, s3);
}

// ---------------------------------------------------------------------------
extern "C" void kernel_launch(void* const* d_in, const int* in_sizes, int n_in,
                              void* d_out, int out_size) {
    const float* node_sca = (const float*)d_in[0];
    const float* node_vec = (const float*)d_in[1];
    const float* edge_sca = (const float*)d_in[2];
    const float* edge_vec = (const float*)d_in[3];
    const float* gds      = (const float*)d_in[4];
    const int*   ei       = (const int*)d_in[5];   // [2,E]; row 0 = src
    const float* W_nss  = (const float*)d_in[6];
    const float* b_nss  = (const float*)d_in[7];
    const float* W_ess  = (const float*)d_in[8];
    const float* b_ess  = (const float*)d_in[9];
    const float* W_nsv  = (const float*)d_in[10];
    const float* b_nsv  = (const float*)d_in[11];
    const float* W_esv  = (const float*)d_in[12];
    const float* b_esv  = (const float*)d_in[13];
    const float* W_nvv  = (const float*)d_in[14];
    const float* W_evv  = (const float*)d_in[15];
    const float* W_lv   = (const float*)d_in[16];
    const float* W_lv2  = (const float*)d_in[17];
    const float* W_ls   = (const float*)d_in[18];
    const float* W_gate = (const float*)d_in[19];
    const float* b_gate = (const float*)d_in[20];
    const float* W_dir  = (const float*)d_in[21];

    int N = in_sizes[0] / 4;
    int E = in_sizes[4];

    int eblocks = (E + EPB - 1) / EPB;
    edge_kernel<<<eblocks, EPB>>>(edge_sca, edge_vec, gds, ei, E);

    int nblocks = (N + NPB - 1) / NPB;
    node_kernel<<<nblocks, TPB>>>(node_sca, node_vec,
                                  W_nss, b_nss, W_ess, b_ess,
                                  W_nsv, b_nsv, W_esv, b_esv,
                                  W_nvv, W_evv, W_lv, W_lv2,
                                  W_ls, W_gate, b_gate, W_dir,
                                  (float*)d_out, N);
}